// round 10
// baseline (speedup 1.0000x reference)
#include <cuda_runtime.h>
#include <math.h>
#include <float.h>

#define NT    256
#define EPT   16          // elements per thread (fast path covers N <= NT*EPT = 4096)
#define MAXK  128
#define GNT   1024        // generic-path threads
#define NWARP (NT/32)

// Exactly replicates the reference's per-element float32 computation:
//   avg = s/200 ; sig = sqrt(-2/log(1-avg^2)) ; sig2 = sig^2  (sqrt-then-square!)
__device__ __forceinline__ float sig2_of_sum(float s) {
    float avg = s / 200.0f;
    float l   = logf(1.0f - avg * avg);
    float v   = -2.0f / l;
    float sg  = sqrtf(v);
    return sg * sg;
}

// Fast approximate sig2 (MUFU __logf). Used ONLY for the conservative
// pre-filter threshold, never for classification.
__device__ __forceinline__ float sig2_fast(float s) {
    float avg = s * 0.005f;
    float l   = __logf(1.0f - avg * avg);
    return -2.0f / l;
}

// Order-preserving float->uint encoding (total order, incl. negatives)
__device__ __forceinline__ unsigned fenc(float f) {
    unsigned u = __float_as_uint(f);
    return u ^ ((u >> 31) ? 0xFFFFFFFFu : 0x80000000u);
}
__device__ __forceinline__ float fdec(unsigned e) {
    unsigned u = (e & 0x80000000u) ? (e ^ 0x80000000u) : ~e;
    return __uint_as_float(u);
}

// merge (a1<=a2) with (b1<=b2) -> two smallest, in place
__device__ __forceinline__ void mrg2min(float& a1, float& a2, float b1, float b2) {
    float n1 = fminf(a1, b1);
    float n2 = fminf(fmaxf(a1, b1), fminf(a2, b2));
    a1 = n1; a2 = n2;
}
// merge (a1>=a2) with (b1>=b2) -> two largest, in place
__device__ __forceinline__ void mrg2max(float& a1, float& a2, float b1, float b2) {
    float n1 = fmaxf(a1, b1);
    float n2 = fmaxf(fminf(a1, b1), fmaxf(a2, b2));
    a1 = n1; a2 = n2;
}

// Warp-wide "two smallest" from per-lane sorted (e1<=e2), encoded uints. All lanes.
__device__ __forceinline__ void warp2min(unsigned e1, unsigned e2,
                                         unsigned& g1, unsigned& g2) {
    const unsigned FULL = 0xFFFFFFFFu;
    g1 = __reduce_min_sync(FULL, e1);
    unsigned bal = __ballot_sync(FULL, e1 == g1);
    int leader = __ffs(bal) - 1;
    unsigned w = ((int)(threadIdx.x & 31) == leader) ? e2 : e1;
    g2 = __reduce_min_sync(FULL, w);
}
__device__ __forceinline__ void warp2max(unsigned e1, unsigned e2,
                                         unsigned& g1, unsigned& g2) {
    const unsigned FULL = 0xFFFFFFFFu;
    g1 = __reduce_max_sync(FULL, e1);
    unsigned bal = __ballot_sync(FULL, e1 == g1);
    int leader = __ffs(bal) - 1;
    unsigned w = ((int)(threadIdx.x & 31) == leader) ? e2 : e1;
    g2 = __reduce_max_sync(FULL, w);
}

// Conservative per-index sigma threshold (EXACT-math version, generic path).
__device__ __forceinline__ float make_sigth(float begin, float interval, float m1) {
    float th = (begin + 9.0f * interval) * 0.999f;       // conservative margin
    if (th > 0.0f && interval > 0.0f) {
        float u     = -expm1f(-2.0f / th);               // 1 - exp(-2/th)
        float avg_b = sqrtf(fmaxf(u, 0.0f)) * 1.002f;
        float sum_b = avg_b * 200.0f + 0.01f;            // loose sum bound
        return sum_b - m1;                               // per-index bound
    }
    return FLT_MAX;                                      // degenerate: admit all
}

// Conservative per-index sigma threshold, FAST-MATH version with widened
// margins. Every approximation errs toward ADMITTING MORE:
//  - th underestimates the exact bin-9 boundary (0.995 dominates __logf err)
//  - u = min(1.0005*x, 1) >= 1 - e^{-x} always
//  - avg_b *1.01, sum_b +0.05 widen further
// Over-admission only grows the candidate set; exact classification in the
// tail is unaffected. Overflow -> exact all-pairs fallback.
__device__ __forceinline__ float make_sigth_fast(float ba, float ea, float m1) {
    float th = (0.1f * ba + 0.9f * ea) * 0.995f;
    if (th > 0.0f && ea > ba) {
        float x     = 2.0f / th;
        float u     = fminf(x * 1.0005f, 1.0f);          // >= 1 - exp(-x)
        float avg_b = sqrtf(u) * 1.01f;
        float sum_b = avg_b * 200.0f + 0.05f;
        return sum_b - m1;
    }
    return FLT_MAX;                                      // degenerate: admit all
}

// ============================ FAST PATH (N <= NT*EPT) ============================
__global__ __launch_bounds__(NT, 1)
void ENCELDDT_fast(const float* __restrict__ sigmas,
                   const float* __restrict__ y,
                   const float* __restrict__ py,
                   float* __restrict__ out, int N)
{
    __shared__ unsigned red[NWARP][4];           // per-warp encoded (m1,m2,M1,M2)
    __shared__ int   s_count;
    __shared__ unsigned long long s_key[MAXK];   // (idx<<32)|slot
    __shared__ int   s_ord[MAXK];                // slot in idx order
    __shared__ float s_val[MAXK];
    __shared__ float s_crd[MAXK][6];
    __shared__ float fb[NWARP][3];               // degenerate-path reduce

    const int tid  = threadIdx.x;
    const int lane = tid & 31;
    const int wrp  = tid >> 5;
    const unsigned FULL = 0xFFFFFFFFu;
    const int base = tid * EPT;
    const bool full = (base + EPT <= N);

    if (tid == 0) s_count = 0;

    // ---- load EPT owned elements into registers (4x LDG.128 when full) ----
    float v[EPT];
    if (full) {
        #pragma unroll
        for (int q = 0; q < EPT / 4; q++) {
            float4 a = *reinterpret_cast<const float4*>(sigmas + base + 4 * q);
            v[4*q] = a.x; v[4*q+1] = a.y; v[4*q+2] = a.z; v[4*q+3] = a.w;
        }
    } else {
        #pragma unroll
        for (int k = 0; k < EPT; k++)
            v[k] = (base + k < N) ? sigmas[base + k] : 0.0f;
    }

    // ---- fire-and-forget L2 prefetch of y/py (covers cold-L2 replays) ----
    {
        const char* yb  = (const char*)y;
        const char* pyb = (const char*)py;
        long ybytes = (long)N * 3 * sizeof(float);
        for (long off = (long)tid * 128; off < ybytes; off += (long)NT * 128) {
            asm volatile("prefetch.global.L2 [%0];" :: "l"(yb  + off));
            asm volatile("prefetch.global.L2 [%0];" :: "l"(pyb + off));
        }
    }

    // ---- thread-local min2/max2: one pair-sort layer + log-depth merge trees ----
    float m1, m2, M1, M2;
    if (full) {
        float a1[EPT/2], a2[EPT/2], b1[EPT/2], b2[EPT/2];
        #pragma unroll
        for (int k = 0; k < EPT/2; k++) {
            float lo = fminf(v[2*k], v[2*k+1]);
            float hi = fmaxf(v[2*k], v[2*k+1]);
            a1[k] = lo; a2[k] = hi;      // ascending (min side)
            b1[k] = hi; b2[k] = lo;      // descending (max side)
        }
        #pragma unroll
        for (int step = 1; step < EPT/2; step <<= 1) {
            #pragma unroll
            for (int k = 0; k + step < EPT/2; k += 2*step) {
                mrg2min(a1[k], a2[k], a1[k+step], a2[k+step]);
                mrg2max(b1[k], b2[k], b1[k+step], b2[k+step]);
            }
        }
        m1 = a1[0]; m2 = a2[0]; M1 = b1[0]; M2 = b2[0];
    } else {
        float q1 = FLT_MAX, q2 = FLT_MAX, s1 = -FLT_MAX, s2 = -FLT_MAX;
        #pragma unroll
        for (int k = 0; k < EPT; k++) {
            if (base + k < N) {
                float a = v[k];
                mrg2min(q1, q2, a, FLT_MAX);
                mrg2max(s1, s2, a, -FLT_MAX);
            }
        }
        m1 = q1; m2 = q2; M1 = s1; M2 = s2;
    }

    // ---- warp-level merge via REDUX on encoded values ----
    unsigned wm1, wm2, wM1, wM2;
    warp2min(fenc(m1), fenc(m2), wm1, wm2);
    warp2max(fenc(M1), fenc(M2), wM1, wM2);
    if (lane == 0) {
        red[wrp][0] = wm1; red[wrp][1] = wm2;
        red[wrp][2] = wM1; red[wrp][3] = wM2;
    }
    __syncthreads();                                           // barrier 1 (of 2)

    // ---- every warp merges + computes the FAST threshold; ONLY warp 0 also
    //      runs the exact begin/end chain (sole tail consumer; overlaps phase B) -
    float begin = 0.0f, interval = 0.0f, sigth;
    float minsum, maxsum, gm1;
    {
        unsigned e1 = (lane < NWARP) ? red[lane][0] : 0xFFFFFFFFu;
        unsigned e2 = (lane < NWARP) ? red[lane][1] : 0xFFFFFFFFu;
        unsigned f1 = (lane < NWARP) ? red[lane][2] : 0u;
        unsigned f2 = (lane < NWARP) ? red[lane][3] : 0u;
        unsigned gm1e, gm2e, gM1e, gM2e;
        warp2min(e1, e2, gm1e, gm2e);
        warp2max(f1, f2, gM1e, gM2e);
        gm1 = fdec(gm1e);
        float gm2 = fdec(gm2e);
        float gM1 = fdec(gM1e), gM2 = fdec(gM2e);
        minsum = gm1 + gm2; maxsum = gM1 + gM2;

        // fast conservative threshold (short MUFU chain; phase B depends on THIS)
        float ba = sig2_fast(maxsum);
        float ea = sig2_fast(minsum);
        sigth = make_sigth_fast(ba, ea, gm1);

        if (wrp == 0) {
            // exact begin/end (reference math; lanes 0/1 in parallel); consumed
            // only after barrier 2 -> latency hides under phase B
            float t = sig2_of_sum((lane & 1) ? minsum : maxsum);
            begin     = __shfl_sync(FULL, t, 0);   // sig2 decreasing in sum
            float end = __shfl_sync(FULL, t, 1);
            interval  = (end - begin) / 10.0f;
        }
    }

    // ---- phase B: test registers vs threshold; gather + coord fetch ----
    #pragma unroll
    for (int k = 0; k < EPT; k++) {
        int idx = base + k;
        if (v[k] <= sigth && (full || idx < N)) {
            int p = atomicAdd(&s_count, 1);
            if (p < MAXK) {
                s_key[p] = ((unsigned long long)(unsigned)idx << 32) | (unsigned)p;
                s_val[p] = v[k];
                s_crd[p][0] = __ldg(y  + 3*idx);  s_crd[p][1] = __ldg(y  + 3*idx + 1);
                s_crd[p][2] = __ldg(y  + 3*idx + 2);
                s_crd[p][3] = __ldg(py + 3*idx);  s_crd[p][4] = __ldg(py + 3*idx + 1);
                s_crd[p][5] = __ldg(py + 3*idx + 2);
            }
        }
    }
    __syncthreads();                                           // barrier 2 (of 2)

    const int K = s_count;

    if (K <= MAXK) {
        if (wrp != 0) return;                  // warp 0 finishes alone

        // deterministic idx-order: parallel rank sort for K<=32, serial otherwise
        if (K <= 32) {
            if (lane < K) {
                unsigned long long mine = s_key[lane];
                int rank = 0;
                for (int a = 0; a < K; a++) rank += (s_key[a] < mine) ? 1 : 0;
                s_ord[rank] = (int)(unsigned)(mine & 0xFFFFFFFFull);
            }
        } else if (lane == 0) {
            for (int a = 1; a < K; a++) {
                unsigned long long kv = s_key[a];
                int b = a - 1;
                while (b >= 0 && s_key[b] > kv) { s_key[b + 1] = s_key[b]; b--; }
                s_key[b + 1] = kv;
            }
            for (int a = 0; a < K; a++) s_ord[a] = (int)(unsigned)(s_key[a] & 0xFFFFFFFFull);
        }
        __syncwarp();

        // Unordered pairs only: (i,j)/(j,i) contribute identically; the factor
        // 2 cancels in ss/cnt and st/cnt.
        float cnt = 0.0f, ss = 0.0f, st = 0.0f;
        int T = (K * (K - 1)) >> 1;
        for (int p = lane; p < T; p += 32) {
            int a = 0, r = p;
            while (r >= K - 1 - a) { r -= K - 1 - a; a++; }   // triangular decode
            int b = a + 1 + r;
            int sa = s_ord[a], sb = s_ord[b];
            float sig2 = sig2_of_sum(s_val[sa] + s_val[sb]);
            float t    = (sig2 - begin) / interval;
            int bi = (int)floorf(t);
            bi = bi < 0 ? 0 : (bi > 9 ? 9 : bi);
            if (bi == 9) {
                float dx = s_crd[sa][0] - s_crd[sb][0];
                float dy = s_crd[sa][1] - s_crd[sb][1];
                float dz = s_crd[sa][2] - s_crd[sb][2];
                float dg = sqrtf(dx*dx + dy*dy + dz*dz);
                float ex = s_crd[sa][3] - s_crd[sb][3];
                float ey = s_crd[sa][4] - s_crd[sb][4];
                float ez = s_crd[sa][5] - s_crd[sb][5];
                float dp = sqrtf(ex*ex + ey*ey + ez*ez);
                float tr = dg - dp;
                cnt += 1.0f; ss += sig2; st += tr * tr;
            }
        }
        #pragma unroll
        for (int off = 16; off; off >>= 1) {
            cnt += __shfl_down_sync(FULL, cnt, off);
            ss  += __shfl_down_sync(FULL, ss,  off);
            st  += __shfl_down_sync(FULL, st,  off);
        }
        if (lane == 0) {
            float mvar = sqrtf(ss / cnt);      // cnt >= 1: min-sum pair is bin 9
            float rmse = sqrtf(st / cnt);
            out[0] = fabsf(mvar - rmse) / mvar;
        }
        return;
    }

    // ---- overflow fallback (K > MAXK): exact all-pairs, all threads ----
    {
        // recompute exact begin/interval locally (warps 1..7 skipped it above)
        begin     = sig2_of_sum(maxsum);
        float end = sig2_of_sum(minsum);
        interval  = (end - begin) / 10.0f;

        float cnt = 0.0f, ss = 0.0f, st = 0.0f;
        long total = (long)N * (long)N;
        for (long p = tid; p < total; p += NT) {
            int i = (int)(p / N), j = (int)(p - (long)i * N);
            if (i == j) continue;
            float sig2 = sig2_of_sum(__ldg(sigmas + i) + __ldg(sigmas + j));
            float t    = (sig2 - begin) / interval;
            int bi = (int)floorf(t);
            bi = bi < 0 ? 0 : (bi > 9 ? 9 : bi);
            if (bi == 9) {
                float dx = y[3*i]-y[3*j], dy = y[3*i+1]-y[3*j+1], dz = y[3*i+2]-y[3*j+2];
                float dg = sqrtf(dx*dx + dy*dy + dz*dz);
                float ex = py[3*i]-py[3*j], ey = py[3*i+1]-py[3*j+1], ez = py[3*i+2]-py[3*j+2];
                float dp = sqrtf(ex*ex + ey*ey + ez*ez);
                float tr = dg - dp;
                cnt += 1.0f; ss += sig2; st += tr * tr;
            }
        }
        #pragma unroll
        for (int off = 16; off; off >>= 1) {
            cnt += __shfl_down_sync(FULL, cnt, off);
            ss  += __shfl_down_sync(FULL, ss,  off);
            st  += __shfl_down_sync(FULL, st,  off);
        }
        if (lane == 0) { fb[wrp][0] = cnt; fb[wrp][1] = ss; fb[wrp][2] = st; }
        __syncthreads();
        if (wrp == 0) {
            cnt = (lane < NWARP) ? fb[lane][0] : 0.0f;
            ss  = (lane < NWARP) ? fb[lane][1] : 0.0f;
            st  = (lane < NWARP) ? fb[lane][2] : 0.0f;
            #pragma unroll
            for (int off = 16; off; off >>= 1) {
                cnt += __shfl_down_sync(FULL, cnt, off);
                ss  += __shfl_down_sync(FULL, ss,  off);
                st  += __shfl_down_sync(FULL, st,  off);
            }
            if (lane == 0) {
                float mvar = sqrtf(ss / cnt);
                float rmse = sqrtf(st / cnt);
                out[0] = fabsf(mvar - rmse) / mvar;
            }
        }
    }
}

// ==================== GENERIC PATH (N > NT*EPT; strided) ====================
__device__ __forceinline__ void upd_minmax(float v, float& m1, float& m2,
                                           float& M1, float& M2) {
    if (v < m1) { m2 = m1; m1 = v; } else if (v < m2) { m2 = v; }
    if (v > M1) { M2 = M1; M1 = v; } else if (v > M2) { M2 = v; }
}

__global__ __launch_bounds__(GNT, 1)
void ENCELDDT_generic(const float* __restrict__ sigmas,
                      const float* __restrict__ y,
                      const float* __restrict__ py,
                      float* __restrict__ out, int N)
{
    __shared__ float red[32][4];
    __shared__ float s_begin, s_interval, s_sigth;
    __shared__ int   s_count;
    __shared__ unsigned long long s_key[MAXK];
    __shared__ float s_val[MAXK];

    const int tid = threadIdx.x;
    const unsigned FULL = 0xFFFFFFFFu;

    float m1 = FLT_MAX, m2 = FLT_MAX, M1 = -FLT_MAX, M2 = -FLT_MAX;
    for (int i = tid; i < N; i += GNT) upd_minmax(sigmas[i], m1, m2, M1, M2);
    #pragma unroll
    for (int off = 16; off; off >>= 1) {
        float a1 = __shfl_down_sync(FULL, m1, off);
        float a2 = __shfl_down_sync(FULL, m2, off);
        mrg2min(m1, m2, a1, a2);
        float b1 = __shfl_down_sync(FULL, M1, off);
        float b2 = __shfl_down_sync(FULL, M2, off);
        mrg2max(M1, M2, b1, b2);
    }
    if ((tid & 31) == 0) { red[tid>>5][0]=m1; red[tid>>5][1]=m2; red[tid>>5][2]=M1; red[tid>>5][3]=M2; }
    __syncthreads();
    if (tid < 32) {
        m1 = red[tid][0]; m2 = red[tid][1]; M1 = red[tid][2]; M2 = red[tid][3];
        #pragma unroll
        for (int off = 16; off; off >>= 1) {
            float a1 = __shfl_down_sync(FULL, m1, off);
            float a2 = __shfl_down_sync(FULL, m2, off);
            mrg2min(m1, m2, a1, a2);
            float b1 = __shfl_down_sync(FULL, M1, off);
            float b2 = __shfl_down_sync(FULL, M2, off);
            mrg2max(M1, M2, b1, b2);
        }
        if (tid == 0) {
            float begin    = sig2_of_sum(M1 + M2);
            float end      = sig2_of_sum(m1 + m2);
            float interval = (end - begin) / 10.0f;
            s_begin = begin; s_interval = interval;
            s_sigth = make_sigth(begin, interval, m1);
            s_count = 0;
        }
    }
    __syncthreads();

    const float sigth = s_sigth;
    for (int i = tid; i < N; i += GNT) {
        float v = sigmas[i];
        if (v <= sigth) {
            int p = atomicAdd(&s_count, 1);
            if (p < MAXK) {
                s_key[p] = ((unsigned long long)(unsigned)i << 32) | (unsigned)p;
                s_val[p] = v;
            }
        }
    }
    __syncthreads();

    const int K = s_count;
    const float begin = s_begin, interval = s_interval;

    if (K <= MAXK) {
        if (tid >= 32) return;
        if (tid == 0) {
            for (int a = 1; a < K; a++) {
                unsigned long long kv = s_key[a];
                int b = a - 1;
                while (b >= 0 && s_key[b] > kv) { s_key[b + 1] = s_key[b]; b--; }
                s_key[b + 1] = kv;
            }
        }
        __syncwarp();
        float cnt = 0.0f, ss = 0.0f, st = 0.0f;
        int T = (K * (K - 1)) >> 1;                      // unordered pairs (2x cancels)
        for (int p = tid; p < T; p += 32) {
            int a = 0, r = p;
            while (r >= K - 1 - a) { r -= K - 1 - a; a++; }
            int b = a + 1 + r;
            int i = (int)(s_key[a] >> 32), j = (int)(s_key[b] >> 32);
            int sa = (int)(unsigned)(s_key[a] & 0xFFFFFFFFull);
            int sb = (int)(unsigned)(s_key[b] & 0xFFFFFFFFull);
            float sig2 = sig2_of_sum(s_val[sa] + s_val[sb]);
            float t = (sig2 - begin) / interval;
            int bi = (int)floorf(t);
            bi = bi < 0 ? 0 : (bi > 9 ? 9 : bi);
            if (bi == 9) {
                float dx = y[3*i]-y[3*j], dy = y[3*i+1]-y[3*j+1], dz = y[3*i+2]-y[3*j+2];
                float dg = sqrtf(dx*dx + dy*dy + dz*dz);
                float ex = py[3*i]-py[3*j], ey = py[3*i+1]-py[3*j+1], ez = py[3*i+2]-py[3*j+2];
                float dp = sqrtf(ex*ex + ey*ey + ez*ez);
                float tr = dg - dp;
                cnt += 1.0f; ss += sig2; st += tr * tr;
            }
        }
        #pragma unroll
        for (int off = 16; off; off >>= 1) {
            cnt += __shfl_down_sync(FULL, cnt, off);
            ss  += __shfl_down_sync(FULL, ss,  off);
            st  += __shfl_down_sync(FULL, st,  off);
        }
        if (tid == 0) {
            float mvar = sqrtf(ss / cnt);
            float rmse = sqrtf(st / cnt);
            out[0] = fabsf(mvar - rmse) / mvar;
        }
        return;
    }

    {   // degenerate fallback: exact all-pairs
        float cnt = 0.0f, ss = 0.0f, st = 0.0f;
        long total = (long)N * (long)N;
        for (long p = tid; p < total; p += GNT) {
            int i = (int)(p / N), j = (int)(p - (long)i * N);
            if (i == j) continue;
            float sig2 = sig2_of_sum(__ldg(sigmas + i) + __ldg(sigmas + j));
            float t = (sig2 - begin) / interval;
            int bi = (int)floorf(t);
            bi = bi < 0 ? 0 : (bi > 9 ? 9 : bi);
            if (bi == 9) {
                float dx = y[3*i]-y[3*j], dy = y[3*i+1]-y[3*j+1], dz = y[3*i+2]-y[3*j+2];
                float dg = sqrtf(dx*dx + dy*dy + dz*dz);
                float ex = py[3*i]-py[3*j], ey = py[3*i+1]-py[3*j+1], ez = py[3*i+2]-py[3*j+2];
                float dp = sqrtf(ex*ex + ey*ey + ez*ez);
                float tr = dg - dp;
                cnt += 1.0f; ss += sig2; st += tr * tr;
            }
        }
        #pragma unroll
        for (int off = 16; off; off >>= 1) {
            cnt += __shfl_down_sync(FULL, cnt, off);
            ss  += __shfl_down_sync(FULL, ss,  off);
            st  += __shfl_down_sync(FULL, st,  off);
        }
        if ((tid & 31) == 0) { red[tid>>5][0]=cnt; red[tid>>5][1]=ss; red[tid>>5][2]=st; }
        __syncthreads();
        if (tid < 32) {
            cnt = red[tid][0]; ss = red[tid][1]; st = red[tid][2];
            #pragma unroll
            for (int off = 16; off; off >>= 1) {
                cnt += __shfl_down_sync(FULL, cnt, off);
                ss  += __shfl_down_sync(FULL, ss,  off);
                st  += __shfl_down_sync(FULL, st,  off);
            }
            if (tid == 0) {
                float mvar = sqrtf(ss / cnt);
                float rmse = sqrtf(st / cnt);
                out[0] = fabsf(mvar - rmse) / mvar;
            }
        }
    }
}

extern "C" void kernel_launch(void* const* d_in, const int* in_sizes, int n_in,
                              void* d_out, int out_size) {
    const float* sigmas = (const float*)d_in[0];
    const float* y      = (const float*)d_in[1];
    const float* py     = (const float*)d_in[2];
    int N = in_sizes[0];
    if (N <= NT * EPT)
        ENCELDDT_fast<<<1, NT>>>(sigmas, y, py, (float*)d_out, N);
    else
        ENCELDDT_generic<<<1, GNT>>>(sigmas, y, py, (float*)d_out, N);
}

// round 11
// speedup vs baseline: 1.0036x; 1.0036x over previous
#include <cuda_runtime.h>
#include <math.h>
#include <float.h>

#define NT    128
#define EPT   32          // elements per thread (fast path covers N <= NT*EPT = 4096)
#define MAXK  128
#define GNT   1024        // generic-path threads
#define NWARP (NT/32)

// Exactly replicates the reference's per-element float32 computation:
//   avg = s/200 ; sig = sqrt(-2/log(1-avg^2)) ; sig2 = sig^2  (sqrt-then-square!)
__device__ __forceinline__ float sig2_of_sum(float s) {
    float avg = s / 200.0f;
    float l   = logf(1.0f - avg * avg);
    float v   = -2.0f / l;
    float sg  = sqrtf(v);
    return sg * sg;
}

// Fast approximate sig2 (MUFU __logf). Used ONLY for the conservative
// pre-filter threshold, never for classification.
__device__ __forceinline__ float sig2_fast(float s) {
    float avg = s * 0.005f;
    float l   = __logf(1.0f - avg * avg);
    return -2.0f / l;
}

// Order-preserving float->uint encoding (total order, incl. negatives)
__device__ __forceinline__ unsigned fenc(float f) {
    unsigned u = __float_as_uint(f);
    return u ^ ((u >> 31) ? 0xFFFFFFFFu : 0x80000000u);
}
__device__ __forceinline__ float fdec(unsigned e) {
    unsigned u = (e & 0x80000000u) ? (e ^ 0x80000000u) : ~e;
    return __uint_as_float(u);
}

// merge (a1<=a2) with (b1<=b2) -> two smallest, in place
__device__ __forceinline__ void mrg2min(float& a1, float& a2, float b1, float b2) {
    float n1 = fminf(a1, b1);
    float n2 = fminf(fmaxf(a1, b1), fminf(a2, b2));
    a1 = n1; a2 = n2;
}
// merge (a1>=a2) with (b1>=b2) -> two largest, in place
__device__ __forceinline__ void mrg2max(float& a1, float& a2, float b1, float b2) {
    float n1 = fmaxf(a1, b1);
    float n2 = fmaxf(fminf(a1, b1), fmaxf(a2, b2));
    a1 = n1; a2 = n2;
}

// Warp-wide "two smallest" from per-lane sorted (e1<=e2), encoded uints. All lanes.
__device__ __forceinline__ void warp2min(unsigned e1, unsigned e2,
                                         unsigned& g1, unsigned& g2) {
    const unsigned FULL = 0xFFFFFFFFu;
    g1 = __reduce_min_sync(FULL, e1);
    unsigned bal = __ballot_sync(FULL, e1 == g1);
    int leader = __ffs(bal) - 1;
    unsigned w = ((int)(threadIdx.x & 31) == leader) ? e2 : e1;
    g2 = __reduce_min_sync(FULL, w);
}
__device__ __forceinline__ void warp2max(unsigned e1, unsigned e2,
                                         unsigned& g1, unsigned& g2) {
    const unsigned FULL = 0xFFFFFFFFu;
    g1 = __reduce_max_sync(FULL, e1);
    unsigned bal = __ballot_sync(FULL, e1 == g1);
    int leader = __ffs(bal) - 1;
    unsigned w = ((int)(threadIdx.x & 31) == leader) ? e2 : e1;
    g2 = __reduce_max_sync(FULL, w);
}

// Conservative per-index sigma threshold (EXACT-math version, generic path).
__device__ __forceinline__ float make_sigth(float begin, float interval, float m1) {
    float th = (begin + 9.0f * interval) * 0.999f;       // conservative margin
    if (th > 0.0f && interval > 0.0f) {
        float u     = -expm1f(-2.0f / th);               // 1 - exp(-2/th)
        float avg_b = sqrtf(fmaxf(u, 0.0f)) * 1.002f;
        float sum_b = avg_b * 200.0f + 0.01f;            // loose sum bound
        return sum_b - m1;                               // per-index bound
    }
    return FLT_MAX;                                      // degenerate: admit all
}

// Conservative per-index sigma threshold, FAST-MATH version with widened
// margins. Every approximation errs toward ADMITTING MORE:
//  - th underestimates the exact bin-9 boundary (0.995 dominates __logf err)
//  - u = min(1.0005*x, 1) >= 1 - e^{-x} always
//  - avg_b *1.01, sum_b +0.05 widen further
// Over-admission only grows the candidate set; exact classification in the
// tail is unaffected. Overflow -> exact all-pairs fallback.
__device__ __forceinline__ float make_sigth_fast(float ba, float ea, float m1) {
    float th = (0.1f * ba + 0.9f * ea) * 0.995f;
    if (th > 0.0f && ea > ba) {
        float x     = 2.0f / th;
        float u     = fminf(x * 1.0005f, 1.0f);          // >= 1 - exp(-x)
        float avg_b = sqrtf(u) * 1.01f;
        float sum_b = avg_b * 200.0f + 0.05f;
        return sum_b - m1;
    }
    return FLT_MAX;                                      // degenerate: admit all
}

// ============================ FAST PATH (N <= NT*EPT) ============================
__global__ __launch_bounds__(NT, 1)
void ENCELDDT_fast(const float* __restrict__ sigmas,
                   const float* __restrict__ y,
                   const float* __restrict__ py,
                   float* __restrict__ out, int N)
{
    __shared__ unsigned red[NWARP][4];           // per-warp encoded (m1,m2,M1,M2)
    __shared__ int   s_count;
    __shared__ unsigned long long s_key[MAXK];   // (idx<<32)|slot
    __shared__ int   s_ord[MAXK];                // slot in idx order
    __shared__ float s_val[MAXK];
    __shared__ float s_crd[MAXK][6];
    __shared__ float fb[NWARP][3];               // degenerate-path reduce

    const int tid  = threadIdx.x;
    const int lane = tid & 31;
    const int wrp  = tid >> 5;
    const unsigned FULL = 0xFFFFFFFFu;
    const int base = tid * EPT;
    const bool full = (base + EPT <= N);

    if (tid == 0) s_count = 0;

    // ---- load EPT owned elements into registers (8x LDG.128 when full) ----
    float v[EPT];
    if (full) {
        #pragma unroll
        for (int q = 0; q < EPT / 4; q++) {
            float4 a = *reinterpret_cast<const float4*>(sigmas + base + 4 * q);
            v[4*q] = a.x; v[4*q+1] = a.y; v[4*q+2] = a.z; v[4*q+3] = a.w;
        }
    } else {
        #pragma unroll
        for (int k = 0; k < EPT; k++)
            v[k] = (base + k < N) ? sigmas[base + k] : 0.0f;
    }

    // ---- fire-and-forget L2 prefetch of y/py (covers cold-L2 replays) ----
    {
        const char* yb  = (const char*)y;
        const char* pyb = (const char*)py;
        long ybytes = (long)N * 3 * sizeof(float);
        for (long off = (long)tid * 128; off < ybytes; off += (long)NT * 128) {
            asm volatile("prefetch.global.L2 [%0];" :: "l"(yb  + off));
            asm volatile("prefetch.global.L2 [%0];" :: "l"(pyb + off));
        }
    }

    // ---- thread-local min2/max2: one pair-sort layer + log-depth merge trees ----
    float m1, m2, M1, M2;
    if (full) {
        float a1[EPT/2], a2[EPT/2], b1[EPT/2], b2[EPT/2];
        #pragma unroll
        for (int k = 0; k < EPT/2; k++) {
            float lo = fminf(v[2*k], v[2*k+1]);
            float hi = fmaxf(v[2*k], v[2*k+1]);
            a1[k] = lo; a2[k] = hi;      // ascending (min side)
            b1[k] = hi; b2[k] = lo;      // descending (max side)
        }
        #pragma unroll
        for (int step = 1; step < EPT/2; step <<= 1) {
            #pragma unroll
            for (int k = 0; k + step < EPT/2; k += 2*step) {
                mrg2min(a1[k], a2[k], a1[k+step], a2[k+step]);
                mrg2max(b1[k], b2[k], b1[k+step], b2[k+step]);
            }
        }
        m1 = a1[0]; m2 = a2[0]; M1 = b1[0]; M2 = b2[0];
    } else {
        float q1 = FLT_MAX, q2 = FLT_MAX, s1 = -FLT_MAX, s2 = -FLT_MAX;
        #pragma unroll
        for (int k = 0; k < EPT; k++) {
            if (base + k < N) {
                float a = v[k];
                mrg2min(q1, q2, a, FLT_MAX);
                mrg2max(s1, s2, a, -FLT_MAX);
            }
        }
        m1 = q1; m2 = q2; M1 = s1; M2 = s2;
    }

    // ---- warp-level merge via REDUX on encoded values ----
    unsigned wm1, wm2, wM1, wM2;
    warp2min(fenc(m1), fenc(m2), wm1, wm2);
    warp2max(fenc(M1), fenc(M2), wM1, wM2);
    if (lane == 0) {
        red[wrp][0] = wm1; red[wrp][1] = wm2;
        red[wrp][2] = wM1; red[wrp][3] = wM2;
    }
    __syncthreads();                                           // barrier 1 (of 2)

    // ---- every warp merges + computes the FAST threshold; ONLY warp 0 also
    //      runs the exact begin/end chain (sole tail consumer; overlaps phase B) -
    float begin = 0.0f, interval = 0.0f, sigth;
    float minsum, maxsum, gm1;
    {
        unsigned e1 = (lane < NWARP) ? red[lane][0] : 0xFFFFFFFFu;
        unsigned e2 = (lane < NWARP) ? red[lane][1] : 0xFFFFFFFFu;
        unsigned f1 = (lane < NWARP) ? red[lane][2] : 0u;
        unsigned f2 = (lane < NWARP) ? red[lane][3] : 0u;
        unsigned gm1e, gm2e, gM1e, gM2e;
        warp2min(e1, e2, gm1e, gm2e);
        warp2max(f1, f2, gM1e, gM2e);
        gm1 = fdec(gm1e);
        float gm2 = fdec(gm2e);
        float gM1 = fdec(gM1e), gM2 = fdec(gM2e);
        minsum = gm1 + gm2; maxsum = gM1 + gM2;

        // fast conservative threshold (short MUFU chain; phase B depends on THIS)
        float ba = sig2_fast(maxsum);
        float ea = sig2_fast(minsum);
        sigth = make_sigth_fast(ba, ea, gm1);

        if (wrp == 0) {
            // exact begin/end (reference math; lanes 0/1 in parallel); consumed
            // only after barrier 2 -> latency hides under phase B
            float t = sig2_of_sum((lane & 1) ? minsum : maxsum);
            begin     = __shfl_sync(FULL, t, 0);   // sig2 decreasing in sum
            float end = __shfl_sync(FULL, t, 1);
            interval  = (end - begin) / 10.0f;
        }
    }

    // ---- phase B: test registers vs threshold; gather + coord fetch ----
    #pragma unroll
    for (int k = 0; k < EPT; k++) {
        int idx = base + k;
        if (v[k] <= sigth && (full || idx < N)) {
            int p = atomicAdd(&s_count, 1);
            if (p < MAXK) {
                s_key[p] = ((unsigned long long)(unsigned)idx << 32) | (unsigned)p;
                s_val[p] = v[k];
                s_crd[p][0] = __ldg(y  + 3*idx);  s_crd[p][1] = __ldg(y  + 3*idx + 1);
                s_crd[p][2] = __ldg(y  + 3*idx + 2);
                s_crd[p][3] = __ldg(py + 3*idx);  s_crd[p][4] = __ldg(py + 3*idx + 1);
                s_crd[p][5] = __ldg(py + 3*idx + 2);
            }
        }
    }
    __syncthreads();                                           // barrier 2 (of 2)

    const int K = s_count;

    if (K <= MAXK) {
        if (wrp != 0) return;                  // warp 0 finishes alone

        // deterministic idx-order: parallel rank sort for K<=32, serial otherwise
        if (K <= 32) {
            if (lane < K) {
                unsigned long long mine = s_key[lane];
                int rank = 0;
                for (int a = 0; a < K; a++) rank += (s_key[a] < mine) ? 1 : 0;
                s_ord[rank] = (int)(unsigned)(mine & 0xFFFFFFFFull);
            }
        } else if (lane == 0) {
            for (int a = 1; a < K; a++) {
                unsigned long long kv = s_key[a];
                int b = a - 1;
                while (b >= 0 && s_key[b] > kv) { s_key[b + 1] = s_key[b]; b--; }
                s_key[b + 1] = kv;
            }
            for (int a = 0; a < K; a++) s_ord[a] = (int)(unsigned)(s_key[a] & 0xFFFFFFFFull);
        }
        __syncwarp();

        // Unordered pairs only: (i,j)/(j,i) contribute identically; the factor
        // 2 cancels in ss/cnt and st/cnt.
        float cnt = 0.0f, ss = 0.0f, st = 0.0f;
        int T = (K * (K - 1)) >> 1;
        for (int p = lane; p < T; p += 32) {
            int a = 0, r = p;
            while (r >= K - 1 - a) { r -= K - 1 - a; a++; }   // triangular decode
            int b = a + 1 + r;
            int sa = s_ord[a], sb = s_ord[b];
            float sig2 = sig2_of_sum(s_val[sa] + s_val[sb]);
            float t    = (sig2 - begin) / interval;
            int bi = (int)floorf(t);
            bi = bi < 0 ? 0 : (bi > 9 ? 9 : bi);
            if (bi == 9) {
                float dx = s_crd[sa][0] - s_crd[sb][0];
                float dy = s_crd[sa][1] - s_crd[sb][1];
                float dz = s_crd[sa][2] - s_crd[sb][2];
                float dg = sqrtf(dx*dx + dy*dy + dz*dz);
                float ex = s_crd[sa][3] - s_crd[sb][3];
                float ey = s_crd[sa][4] - s_crd[sb][4];
                float ez = s_crd[sa][5] - s_crd[sb][5];
                float dp = sqrtf(ex*ex + ey*ey + ez*ez);
                float tr = dg - dp;
                cnt += 1.0f; ss += sig2; st += tr * tr;
            }
        }
        #pragma unroll
        for (int off = 16; off; off >>= 1) {
            cnt += __shfl_down_sync(FULL, cnt, off);
            ss  += __shfl_down_sync(FULL, ss,  off);
            st  += __shfl_down_sync(FULL, st,  off);
        }
        if (lane == 0) {
            float mvar = sqrtf(ss / cnt);      // cnt >= 1: min-sum pair is bin 9
            float rmse = sqrtf(st / cnt);
            out[0] = fabsf(mvar - rmse) / mvar;
        }
        return;
    }

    // ---- overflow fallback (K > MAXK): exact all-pairs, all threads ----
    {
        // recompute exact begin/interval locally (warps 1..3 skipped it above)
        begin     = sig2_of_sum(maxsum);
        float end = sig2_of_sum(minsum);
        interval  = (end - begin) / 10.0f;

        float cnt = 0.0f, ss = 0.0f, st = 0.0f;
        long total = (long)N * (long)N;
        for (long p = tid; p < total; p += NT) {
            int i = (int)(p / N), j = (int)(p - (long)i * N);
            if (i == j) continue;
            float sig2 = sig2_of_sum(__ldg(sigmas + i) + __ldg(sigmas + j));
            float t    = (sig2 - begin) / interval;
            int bi = (int)floorf(t);
            bi = bi < 0 ? 0 : (bi > 9 ? 9 : bi);
            if (bi == 9) {
                float dx = y[3*i]-y[3*j], dy = y[3*i+1]-y[3*j+1], dz = y[3*i+2]-y[3*j+2];
                float dg = sqrtf(dx*dx + dy*dy + dz*dz);
                float ex = py[3*i]-py[3*j], ey = py[3*i+1]-py[3*j+1], ez = py[3*i+2]-py[3*j+2];
                float dp = sqrtf(ex*ex + ey*ey + ez*ez);
                float tr = dg - dp;
                cnt += 1.0f; ss += sig2; st += tr * tr;
            }
        }
        #pragma unroll
        for (int off = 16; off; off >>= 1) {
            cnt += __shfl_down_sync(FULL, cnt, off);
            ss  += __shfl_down_sync(FULL, ss,  off);
            st  += __shfl_down_sync(FULL, st,  off);
        }
        if (lane == 0) { fb[wrp][0] = cnt; fb[wrp][1] = ss; fb[wrp][2] = st; }
        __syncthreads();
        if (wrp == 0) {
            cnt = (lane < NWARP) ? fb[lane][0] : 0.0f;
            ss  = (lane < NWARP) ? fb[lane][1] : 0.0f;
            st  = (lane < NWARP) ? fb[lane][2] : 0.0f;
            #pragma unroll
            for (int off = 16; off; off >>= 1) {
                cnt += __shfl_down_sync(FULL, cnt, off);
                ss  += __shfl_down_sync(FULL, ss,  off);
                st  += __shfl_down_sync(FULL, st,  off);
            }
            if (lane == 0) {
                float mvar = sqrtf(ss / cnt);
                float rmse = sqrtf(st / cnt);
                out[0] = fabsf(mvar - rmse) / mvar;
            }
        }
    }
}

// ==================== GENERIC PATH (N > NT*EPT; strided) ====================
__device__ __forceinline__ void upd_minmax(float v, float& m1, float& m2,
                                           float& M1, float& M2) {
    if (v < m1) { m2 = m1; m1 = v; } else if (v < m2) { m2 = v; }
    if (v > M1) { M2 = M1; M1 = v; } else if (v > M2) { M2 = v; }
}

__global__ __launch_bounds__(GNT, 1)
void ENCELDDT_generic(const float* __restrict__ sigmas,
                      const float* __restrict__ y,
                      const float* __restrict__ py,
                      float* __restrict__ out, int N)
{
    __shared__ float red[32][4];
    __shared__ float s_begin, s_interval, s_sigth;
    __shared__ int   s_count;
    __shared__ unsigned long long s_key[MAXK];
    __shared__ float s_val[MAXK];

    const int tid = threadIdx.x;
    const unsigned FULL = 0xFFFFFFFFu;

    float m1 = FLT_MAX, m2 = FLT_MAX, M1 = -FLT_MAX, M2 = -FLT_MAX;
    for (int i = tid; i < N; i += GNT) upd_minmax(sigmas[i], m1, m2, M1, M2);
    #pragma unroll
    for (int off = 16; off; off >>= 1) {
        float a1 = __shfl_down_sync(FULL, m1, off);
        float a2 = __shfl_down_sync(FULL, m2, off);
        mrg2min(m1, m2, a1, a2);
        float b1 = __shfl_down_sync(FULL, M1, off);
        float b2 = __shfl_down_sync(FULL, M2, off);
        mrg2max(M1, M2, b1, b2);
    }
    if ((tid & 31) == 0) { red[tid>>5][0]=m1; red[tid>>5][1]=m2; red[tid>>5][2]=M1; red[tid>>5][3]=M2; }
    __syncthreads();
    if (tid < 32) {
        m1 = red[tid][0]; m2 = red[tid][1]; M1 = red[tid][2]; M2 = red[tid][3];
        #pragma unroll
        for (int off = 16; off; off >>= 1) {
            float a1 = __shfl_down_sync(FULL, m1, off);
            float a2 = __shfl_down_sync(FULL, m2, off);
            mrg2min(m1, m2, a1, a2);
            float b1 = __shfl_down_sync(FULL, M1, off);
            float b2 = __shfl_down_sync(FULL, M2, off);
            mrg2max(M1, M2, b1, b2);
        }
        if (tid == 0) {
            float begin    = sig2_of_sum(M1 + M2);
            float end      = sig2_of_sum(m1 + m2);
            float interval = (end - begin) / 10.0f;
            s_begin = begin; s_interval = interval;
            s_sigth = make_sigth(begin, interval, m1);
            s_count = 0;
        }
    }
    __syncthreads();

    const float sigth = s_sigth;
    for (int i = tid; i < N; i += GNT) {
        float v = sigmas[i];
        if (v <= sigth) {
            int p = atomicAdd(&s_count, 1);
            if (p < MAXK) {
                s_key[p] = ((unsigned long long)(unsigned)i << 32) | (unsigned)p;
                s_val[p] = v;
            }
        }
    }
    __syncthreads();

    const int K = s_count;
    const float begin = s_begin, interval = s_interval;

    if (K <= MAXK) {
        if (tid >= 32) return;
        if (tid == 0) {
            for (int a = 1; a < K; a++) {
                unsigned long long kv = s_key[a];
                int b = a - 1;
                while (b >= 0 && s_key[b] > kv) { s_key[b + 1] = s_key[b]; b--; }
                s_key[b + 1] = kv;
            }
        }
        __syncwarp();
        float cnt = 0.0f, ss = 0.0f, st = 0.0f;
        int T = (K * (K - 1)) >> 1;                      // unordered pairs (2x cancels)
        for (int p = tid; p < T; p += 32) {
            int a = 0, r = p;
            while (r >= K - 1 - a) { r -= K - 1 - a; a++; }
            int b = a + 1 + r;
            int i = (int)(s_key[a] >> 32), j = (int)(s_key[b] >> 32);
            int sa = (int)(unsigned)(s_key[a] & 0xFFFFFFFFull);
            int sb = (int)(unsigned)(s_key[b] & 0xFFFFFFFFull);
            float sig2 = sig2_of_sum(s_val[sa] + s_val[sb]);
            float t = (sig2 - begin) / interval;
            int bi = (int)floorf(t);
            bi = bi < 0 ? 0 : (bi > 9 ? 9 : bi);
            if (bi == 9) {
                float dx = y[3*i]-y[3*j], dy = y[3*i+1]-y[3*j+1], dz = y[3*i+2]-y[3*j+2];
                float dg = sqrtf(dx*dx + dy*dy + dz*dz);
                float ex = py[3*i]-py[3*j], ey = py[3*i+1]-py[3*j+1], ez = py[3*i+2]-py[3*j+2];
                float dp = sqrtf(ex*ex + ey*ey + ez*ez);
                float tr = dg - dp;
                cnt += 1.0f; ss += sig2; st += tr * tr;
            }
        }
        #pragma unroll
        for (int off = 16; off; off >>= 1) {
            cnt += __shfl_down_sync(FULL, cnt, off);
            ss  += __shfl_down_sync(FULL, ss,  off);
            st  += __shfl_down_sync(FULL, st,  off);
        }
        if (tid == 0) {
            float mvar = sqrtf(ss / cnt);
            float rmse = sqrtf(st / cnt);
            out[0] = fabsf(mvar - rmse) / mvar;
        }
        return;
    }

    {   // degenerate fallback: exact all-pairs
        float cnt = 0.0f, ss = 0.0f, st = 0.0f;
        long total = (long)N * (long)N;
        for (long p = tid; p < total; p += GNT) {
            int i = (int)(p / N), j = (int)(p - (long)i * N);
            if (i == j) continue;
            float sig2 = sig2_of_sum(__ldg(sigmas + i) + __ldg(sigmas + j));
            float t = (sig2 - begin) / interval;
            int bi = (int)floorf(t);
            bi = bi < 0 ? 0 : (bi > 9 ? 9 : bi);
            if (bi == 9) {
                float dx = y[3*i]-y[3*j], dy = y[3*i+1]-y[3*j+1], dz = y[3*i+2]-y[3*j+2];
                float dg = sqrtf(dx*dx + dy*dy + dz*dz);
                float ex = py[3*i]-py[3*j], ey = py[3*i+1]-py[3*j+1], ez = py[3*i+2]-py[3*j+2];
                float dp = sqrtf(ex*ex + ey*ey + ez*ez);
                float tr = dg - dp;
                cnt += 1.0f; ss += sig2; st += tr * tr;
            }
        }
        #pragma unroll
        for (int off = 16; off; off >>= 1) {
            cnt += __shfl_down_sync(FULL, cnt, off);
            ss  += __shfl_down_sync(FULL, ss,  off);
            st  += __shfl_down_sync(FULL, st,  off);
        }
        if ((tid & 31) == 0) { red[tid>>5][0]=cnt; red[tid>>5][1]=ss; red[tid>>5][2]=st; }
        __syncthreads();
        if (tid < 32) {
            cnt = red[tid][0]; ss = red[tid][1]; st = red[tid][2];
            #pragma unroll
            for (int off = 16; off; off >>= 1) {
                cnt += __shfl_down_sync(FULL, cnt, off);
                ss  += __shfl_down_sync(FULL, ss,  off);
                st  += __shfl_down_sync(FULL, st,  off);
            }
            if (tid == 0) {
                float mvar = sqrtf(ss / cnt);
                float rmse = sqrtf(st / cnt);
                out[0] = fabsf(mvar - rmse) / mvar;
            }
        }
    }
}

extern "C" void kernel_launch(void* const* d_in, const int* in_sizes, int n_in,
                              void* d_out, int out_size) {
    const float* sigmas = (const float*)d_in[0];
    const float* y      = (const float*)d_in[1];
    const float* py     = (const float*)d_in[2];
    int N = in_sizes[0];
    if (N <= NT * EPT)
        ENCELDDT_fast<<<1, NT>>>(sigmas, y, py, (float*)d_out, N);
    else
        ENCELDDT_generic<<<1, GNT>>>(sigmas, y, py, (float*)d_out, N);
}

// round 12
// speedup vs baseline: 1.0332x; 1.0295x over previous
#include <cuda_runtime.h>
#include <math.h>
#include <float.h>

#define NT    256
#define EPT   16          // elements per thread (fast path covers N <= NT*EPT = 4096)
#define MAXK  128
#define GNT   1024        // generic-path threads
#define NWARP (NT/32)

// Exactly replicates the reference's per-element float32 computation:
//   avg = s/200 ; sig = sqrt(-2/log(1-avg^2)) ; sig2 = sig^2  (sqrt-then-square!)
__device__ __forceinline__ float sig2_of_sum(float s) {
    float avg = s / 200.0f;
    float l   = logf(1.0f - avg * avg);
    float v   = -2.0f / l;
    float sg  = sqrtf(v);
    return sg * sg;
}

// Fast approximate sig2 (MUFU __logf). Used ONLY for the conservative
// pre-filter threshold, never for classification.
__device__ __forceinline__ float sig2_fast(float s) {
    float avg = s * 0.005f;
    float l   = __logf(1.0f - avg * avg);
    return -2.0f / l;
}

// Order-preserving float->uint encoding (total order, incl. negatives)
__device__ __forceinline__ unsigned fenc(float f) {
    unsigned u = __float_as_uint(f);
    return u ^ ((u >> 31) ? 0xFFFFFFFFu : 0x80000000u);
}
__device__ __forceinline__ float fdec(unsigned e) {
    unsigned u = (e & 0x80000000u) ? (e ^ 0x80000000u) : ~e;
    return __uint_as_float(u);
}

// merge (a1<=a2) with (b1<=b2) -> two smallest, in place
__device__ __forceinline__ void mrg2min(float& a1, float& a2, float b1, float b2) {
    float n1 = fminf(a1, b1);
    float n2 = fminf(fmaxf(a1, b1), fminf(a2, b2));
    a1 = n1; a2 = n2;
}
// merge (a1>=a2) with (b1>=b2) -> two largest, in place
__device__ __forceinline__ void mrg2max(float& a1, float& a2, float b1, float b2) {
    float n1 = fmaxf(a1, b1);
    float n2 = fmaxf(fminf(a1, b1), fmaxf(a2, b2));
    a1 = n1; a2 = n2;
}

// Warp-wide "two smallest" from per-lane sorted (e1<=e2), encoded uints. All lanes.
__device__ __forceinline__ void warp2min(unsigned e1, unsigned e2,
                                         unsigned& g1, unsigned& g2) {
    const unsigned FULL = 0xFFFFFFFFu;
    g1 = __reduce_min_sync(FULL, e1);
    unsigned bal = __ballot_sync(FULL, e1 == g1);
    int leader = __ffs(bal) - 1;
    unsigned w = ((int)(threadIdx.x & 31) == leader) ? e2 : e1;
    g2 = __reduce_min_sync(FULL, w);
}
__device__ __forceinline__ void warp2max(unsigned e1, unsigned e2,
                                         unsigned& g1, unsigned& g2) {
    const unsigned FULL = 0xFFFFFFFFu;
    g1 = __reduce_max_sync(FULL, e1);
    unsigned bal = __ballot_sync(FULL, e1 == g1);
    int leader = __ffs(bal) - 1;
    unsigned w = ((int)(threadIdx.x & 31) == leader) ? e2 : e1;
    g2 = __reduce_max_sync(FULL, w);
}

// Conservative per-index sigma threshold (EXACT-math version, generic path).
__device__ __forceinline__ float make_sigth(float begin, float interval, float m1) {
    float th = (begin + 9.0f * interval) * 0.999f;       // conservative margin
    if (th > 0.0f && interval > 0.0f) {
        float u     = -expm1f(-2.0f / th);               // 1 - exp(-2/th)
        float avg_b = sqrtf(fmaxf(u, 0.0f)) * 1.002f;
        float sum_b = avg_b * 200.0f + 0.01f;            // loose sum bound
        return sum_b - m1;                               // per-index bound
    }
    return FLT_MAX;                                      // degenerate: admit all
}

// Conservative per-index sigma threshold, FAST-MATH version with widened
// margins. Every approximation errs toward ADMITTING MORE:
//  - th underestimates the exact bin-9 boundary (0.995 dominates __logf err)
//  - u = min(1.0005*x, 1) >= 1 - e^{-x} always
//  - avg_b *1.01, sum_b +0.05 widen further
// Over-admission only grows the candidate set; exact classification in the
// tail is unaffected. Overflow -> exact all-pairs fallback.
__device__ __forceinline__ float make_sigth_fast(float ba, float ea, float m1) {
    float th = (0.1f * ba + 0.9f * ea) * 0.995f;
    if (th > 0.0f && ea > ba) {
        float x     = 2.0f / th;
        float u     = fminf(x * 1.0005f, 1.0f);          // >= 1 - exp(-x)
        float avg_b = sqrtf(u) * 1.01f;
        float sum_b = avg_b * 200.0f + 0.05f;
        return sum_b - m1;
    }
    return FLT_MAX;                                      // degenerate: admit all
}

// ============================ FAST PATH (N <= NT*EPT) ============================
__global__ __launch_bounds__(NT, 1)
void ENCELDDT_fast(const float* __restrict__ sigmas,
                   const float* __restrict__ y,
                   const float* __restrict__ py,
                   float* __restrict__ out, int N)
{
    __shared__ unsigned red[NWARP][4];           // per-warp encoded (m1,m2,M1,M2)
    __shared__ int   s_count;
    __shared__ unsigned long long s_key[MAXK];   // (idx<<32)|slot
    __shared__ int   s_ord[MAXK];                // slot in idx order
    __shared__ float s_val[MAXK];
    __shared__ float s_crd[MAXK][6];
    __shared__ float fb[NWARP][3];               // degenerate-path reduce

    const int tid  = threadIdx.x;
    const int lane = tid & 31;
    const int wrp  = tid >> 5;
    const unsigned FULL = 0xFFFFFFFFu;
    const int base = tid * EPT;
    const bool full = (base + EPT <= N);

    if (tid == 0) s_count = 0;

    // ---- load EPT owned elements into registers (4x LDG.128 when full) ----
    float v[EPT];
    if (full) {
        #pragma unroll
        for (int q = 0; q < EPT / 4; q++) {
            float4 a = *reinterpret_cast<const float4*>(sigmas + base + 4 * q);
            v[4*q] = a.x; v[4*q+1] = a.y; v[4*q+2] = a.z; v[4*q+3] = a.w;
        }
    } else {
        #pragma unroll
        for (int k = 0; k < EPT; k++)
            v[k] = (base + k < N) ? sigmas[base + k] : 0.0f;
    }

    // ---- fire-and-forget L2 prefetch of y/py (covers cold-L2 replays) ----
    {
        const char* yb  = (const char*)y;
        const char* pyb = (const char*)py;
        long ybytes = (long)N * 3 * sizeof(float);
        for (long off = (long)tid * 128; off < ybytes; off += (long)NT * 128) {
            asm volatile("prefetch.global.L2 [%0];" :: "l"(yb  + off));
            asm volatile("prefetch.global.L2 [%0];" :: "l"(pyb + off));
        }
    }

    // ---- thread-local min2/max2: one pair-sort layer + log-depth merge trees ----
    float m1, m2, M1, M2;
    if (full) {
        float a1[EPT/2], a2[EPT/2], b1[EPT/2], b2[EPT/2];
        #pragma unroll
        for (int k = 0; k < EPT/2; k++) {
            float lo = fminf(v[2*k], v[2*k+1]);
            float hi = fmaxf(v[2*k], v[2*k+1]);
            a1[k] = lo; a2[k] = hi;      // ascending (min side)
            b1[k] = hi; b2[k] = lo;      // descending (max side)
        }
        #pragma unroll
        for (int step = 1; step < EPT/2; step <<= 1) {
            #pragma unroll
            for (int k = 0; k + step < EPT/2; k += 2*step) {
                mrg2min(a1[k], a2[k], a1[k+step], a2[k+step]);
                mrg2max(b1[k], b2[k], b1[k+step], b2[k+step]);
            }
        }
        m1 = a1[0]; m2 = a2[0]; M1 = b1[0]; M2 = b2[0];
    } else {
        float q1 = FLT_MAX, q2 = FLT_MAX, s1 = -FLT_MAX, s2 = -FLT_MAX;
        #pragma unroll
        for (int k = 0; k < EPT; k++) {
            if (base + k < N) {
                float a = v[k];
                mrg2min(q1, q2, a, FLT_MAX);
                mrg2max(s1, s2, a, -FLT_MAX);
            }
        }
        m1 = q1; m2 = q2; M1 = s1; M2 = s2;
    }

    // ---- warp-level merge via REDUX on encoded values ----
    unsigned wm1, wm2, wM1, wM2;
    warp2min(fenc(m1), fenc(m2), wm1, wm2);
    warp2max(fenc(M1), fenc(M2), wM1, wM2);
    if (lane == 0) {
        red[wrp][0] = wm1; red[wrp][1] = wm2;
        red[wrp][2] = wM1; red[wrp][3] = wM2;
    }
    __syncthreads();                                           // barrier 1 (of 2)

    // ---- every warp redundantly merges; FAST sigth unblocks phase B while the
    //      EXACT begin/end chain (consumed only in the tail) overlaps via ILP ----
    float begin, interval, sigth;
    {
        unsigned e1 = (lane < NWARP) ? red[lane][0] : 0xFFFFFFFFu;
        unsigned e2 = (lane < NWARP) ? red[lane][1] : 0xFFFFFFFFu;
        unsigned f1 = (lane < NWARP) ? red[lane][2] : 0u;
        unsigned f2 = (lane < NWARP) ? red[lane][3] : 0u;
        unsigned gm1e, gm2e, gM1e, gM2e;
        warp2min(e1, e2, gm1e, gm2e);
        warp2max(f1, f2, gM1e, gM2e);
        float gm1 = fdec(gm1e), gm2 = fdec(gm2e);
        float gM1 = fdec(gM1e), gM2 = fdec(gM2e);
        float minsum = gm1 + gm2, maxsum = gM1 + gM2;

        // fast conservative threshold (short MUFU chain; phase B depends on THIS)
        float ba = sig2_fast(maxsum);
        float ea = sig2_fast(minsum);
        sigth = make_sigth_fast(ba, ea, gm1);

        // exact begin/end (reference math; lanes 0/1 in parallel); results are
        // consumed only after barrier 2 -> latency hides under phase B
        float t = sig2_of_sum((lane & 1) ? minsum : maxsum);
        begin    = __shfl_sync(FULL, t, 0);        // sig2 decreasing in sum
        float end = __shfl_sync(FULL, t, 1);
        interval = (end - begin) / 10.0f;
    }

    // ---- phase B: test registers vs threshold; gather + coord fetch ----
    #pragma unroll
    for (int k = 0; k < EPT; k++) {
        int idx = base + k;
        if (v[k] <= sigth && (full || idx < N)) {
            int p = atomicAdd(&s_count, 1);
            if (p < MAXK) {
                s_key[p] = ((unsigned long long)(unsigned)idx << 32) | (unsigned)p;
                s_val[p] = v[k];
                s_crd[p][0] = __ldg(y  + 3*idx);  s_crd[p][1] = __ldg(y  + 3*idx + 1);
                s_crd[p][2] = __ldg(y  + 3*idx + 2);
                s_crd[p][3] = __ldg(py + 3*idx);  s_crd[p][4] = __ldg(py + 3*idx + 1);
                s_crd[p][5] = __ldg(py + 3*idx + 2);
            }
        }
    }
    __syncthreads();                                           // barrier 2 (of 2)

    const int K = s_count;

    if (K <= MAXK) {
        if (wrp != 0) return;                  // warp 0 finishes alone

        // deterministic idx-order: parallel rank sort for K<=32, serial otherwise
        if (K <= 32) {
            if (lane < K) {
                unsigned long long mine = s_key[lane];
                int rank = 0;
                for (int a = 0; a < K; a++) rank += (s_key[a] < mine) ? 1 : 0;
                s_ord[rank] = (int)(unsigned)(mine & 0xFFFFFFFFull);
            }
        } else if (lane == 0) {
            for (int a = 1; a < K; a++) {
                unsigned long long kv = s_key[a];
                int b = a - 1;
                while (b >= 0 && s_key[b] > kv) { s_key[b + 1] = s_key[b]; b--; }
                s_key[b + 1] = kv;
            }
            for (int a = 0; a < K; a++) s_ord[a] = (int)(unsigned)(s_key[a] & 0xFFFFFFFFull);
        }
        __syncwarp();

        // Unordered pairs only: (i,j)/(j,i) contribute identically; the factor
        // 2 cancels in ss/cnt and st/cnt.
        float cnt = 0.0f, ss = 0.0f, st = 0.0f;
        int T = (K * (K - 1)) >> 1;
        for (int p = lane; p < T; p += 32) {
            int a = 0, r = p;
            while (r >= K - 1 - a) { r -= K - 1 - a; a++; }   // triangular decode
            int b = a + 1 + r;
            int sa = s_ord[a], sb = s_ord[b];
            float sig2 = sig2_of_sum(s_val[sa] + s_val[sb]);
            float t    = (sig2 - begin) / interval;
            int bi = (int)floorf(t);
            bi = bi < 0 ? 0 : (bi > 9 ? 9 : bi);
            if (bi == 9) {
                float dx = s_crd[sa][0] - s_crd[sb][0];
                float dy = s_crd[sa][1] - s_crd[sb][1];
                float dz = s_crd[sa][2] - s_crd[sb][2];
                float dg = sqrtf(dx*dx + dy*dy + dz*dz);
                float ex = s_crd[sa][3] - s_crd[sb][3];
                float ey = s_crd[sa][4] - s_crd[sb][4];
                float ez = s_crd[sa][5] - s_crd[sb][5];
                float dp = sqrtf(ex*ex + ey*ey + ez*ez);
                float tr = dg - dp;
                cnt += 1.0f; ss += sig2; st += tr * tr;
            }
        }
        #pragma unroll
        for (int off = 16; off; off >>= 1) {
            cnt += __shfl_down_sync(FULL, cnt, off);
            ss  += __shfl_down_sync(FULL, ss,  off);
            st  += __shfl_down_sync(FULL, st,  off);
        }
        if (lane == 0) {
            float mvar = sqrtf(ss / cnt);      // cnt >= 1: min-sum pair is bin 9
            float rmse = sqrtf(st / cnt);
            out[0] = fabsf(mvar - rmse) / mvar;
        }
        return;
    }

    // ---- overflow fallback (K > MAXK): exact all-pairs, all threads ----
    {
        float cnt = 0.0f, ss = 0.0f, st = 0.0f;
        long total = (long)N * (long)N;
        for (long p = tid; p < total; p += NT) {
            int i = (int)(p / N), j = (int)(p - (long)i * N);
            if (i == j) continue;
            float sig2 = sig2_of_sum(__ldg(sigmas + i) + __ldg(sigmas + j));
            float t    = (sig2 - begin) / interval;
            int bi = (int)floorf(t);
            bi = bi < 0 ? 0 : (bi > 9 ? 9 : bi);
            if (bi == 9) {
                float dx = y[3*i]-y[3*j], dy = y[3*i+1]-y[3*j+1], dz = y[3*i+2]-y[3*j+2];
                float dg = sqrtf(dx*dx + dy*dy + dz*dz);
                float ex = py[3*i]-py[3*j], ey = py[3*i+1]-py[3*j+1], ez = py[3*i+2]-py[3*j+2];
                float dp = sqrtf(ex*ex + ey*ey + ez*ez);
                float tr = dg - dp;
                cnt += 1.0f; ss += sig2; st += tr * tr;
            }
        }
        #pragma unroll
        for (int off = 16; off; off >>= 1) {
            cnt += __shfl_down_sync(FULL, cnt, off);
            ss  += __shfl_down_sync(FULL, ss,  off);
            st  += __shfl_down_sync(FULL, st,  off);
        }
        if (lane == 0) { fb[wrp][0] = cnt; fb[wrp][1] = ss; fb[wrp][2] = st; }
        __syncthreads();
        if (wrp == 0) {
            cnt = (lane < NWARP) ? fb[lane][0] : 0.0f;
            ss  = (lane < NWARP) ? fb[lane][1] : 0.0f;
            st  = (lane < NWARP) ? fb[lane][2] : 0.0f;
            #pragma unroll
            for (int off = 16; off; off >>= 1) {
                cnt += __shfl_down_sync(FULL, cnt, off);
                ss  += __shfl_down_sync(FULL, ss,  off);
                st  += __shfl_down_sync(FULL, st,  off);
            }
            if (lane == 0) {
                float mvar = sqrtf(ss / cnt);
                float rmse = sqrtf(st / cnt);
                out[0] = fabsf(mvar - rmse) / mvar;
            }
        }
    }
}

// ==================== GENERIC PATH (N > NT*EPT; strided) ====================
__device__ __forceinline__ void upd_minmax(float v, float& m1, float& m2,
                                           float& M1, float& M2) {
    if (v < m1) { m2 = m1; m1 = v; } else if (v < m2) { m2 = v; }
    if (v > M1) { M2 = M1; M1 = v; } else if (v > M2) { M2 = v; }
}

__global__ __launch_bounds__(GNT, 1)
void ENCELDDT_generic(const float* __restrict__ sigmas,
                      const float* __restrict__ y,
                      const float* __restrict__ py,
                      float* __restrict__ out, int N)
{
    __shared__ float red[32][4];
    __shared__ float s_begin, s_interval, s_sigth;
    __shared__ int   s_count;
    __shared__ unsigned long long s_key[MAXK];
    __shared__ float s_val[MAXK];

    const int tid = threadIdx.x;
    const unsigned FULL = 0xFFFFFFFFu;

    float m1 = FLT_MAX, m2 = FLT_MAX, M1 = -FLT_MAX, M2 = -FLT_MAX;
    for (int i = tid; i < N; i += GNT) upd_minmax(sigmas[i], m1, m2, M1, M2);
    #pragma unroll
    for (int off = 16; off; off >>= 1) {
        float a1 = __shfl_down_sync(FULL, m1, off);
        float a2 = __shfl_down_sync(FULL, m2, off);
        mrg2min(m1, m2, a1, a2);
        float b1 = __shfl_down_sync(FULL, M1, off);
        float b2 = __shfl_down_sync(FULL, M2, off);
        mrg2max(M1, M2, b1, b2);
    }
    if ((tid & 31) == 0) { red[tid>>5][0]=m1; red[tid>>5][1]=m2; red[tid>>5][2]=M1; red[tid>>5][3]=M2; }
    __syncthreads();
    if (tid < 32) {
        m1 = red[tid][0]; m2 = red[tid][1]; M1 = red[tid][2]; M2 = red[tid][3];
        #pragma unroll
        for (int off = 16; off; off >>= 1) {
            float a1 = __shfl_down_sync(FULL, m1, off);
            float a2 = __shfl_down_sync(FULL, m2, off);
            mrg2min(m1, m2, a1, a2);
            float b1 = __shfl_down_sync(FULL, M1, off);
            float b2 = __shfl_down_sync(FULL, M2, off);
            mrg2max(M1, M2, b1, b2);
        }
        if (tid == 0) {
            float begin    = sig2_of_sum(M1 + M2);
            float end      = sig2_of_sum(m1 + m2);
            float interval = (end - begin) / 10.0f;
            s_begin = begin; s_interval = interval;
            s_sigth = make_sigth(begin, interval, m1);
            s_count = 0;
        }
    }
    __syncthreads();

    const float sigth = s_sigth;
    for (int i = tid; i < N; i += GNT) {
        float v = sigmas[i];
        if (v <= sigth) {
            int p = atomicAdd(&s_count, 1);
            if (p < MAXK) {
                s_key[p] = ((unsigned long long)(unsigned)i << 32) | (unsigned)p;
                s_val[p] = v;
            }
        }
    }
    __syncthreads();

    const int K = s_count;
    const float begin = s_begin, interval = s_interval;

    if (K <= MAXK) {
        if (tid >= 32) return;
        if (tid == 0) {
            for (int a = 1; a < K; a++) {
                unsigned long long kv = s_key[a];
                int b = a - 1;
                while (b >= 0 && s_key[b] > kv) { s_key[b + 1] = s_key[b]; b--; }
                s_key[b + 1] = kv;
            }
        }
        __syncwarp();
        float cnt = 0.0f, ss = 0.0f, st = 0.0f;
        int T = (K * (K - 1)) >> 1;                      // unordered pairs (2x cancels)
        for (int p = tid; p < T; p += 32) {
            int a = 0, r = p;
            while (r >= K - 1 - a) { r -= K - 1 - a; a++; }
            int b = a + 1 + r;
            int i = (int)(s_key[a] >> 32), j = (int)(s_key[b] >> 32);
            int sa = (int)(unsigned)(s_key[a] & 0xFFFFFFFFull);
            int sb = (int)(unsigned)(s_key[b] & 0xFFFFFFFFull);
            float sig2 = sig2_of_sum(s_val[sa] + s_val[sb]);
            float t = (sig2 - begin) / interval;
            int bi = (int)floorf(t);
            bi = bi < 0 ? 0 : (bi > 9 ? 9 : bi);
            if (bi == 9) {
                float dx = y[3*i]-y[3*j], dy = y[3*i+1]-y[3*j+1], dz = y[3*i+2]-y[3*j+2];
                float dg = sqrtf(dx*dx + dy*dy + dz*dz);
                float ex = py[3*i]-py[3*j], ey = py[3*i+1]-py[3*j+1], ez = py[3*i+2]-py[3*j+2];
                float dp = sqrtf(ex*ex + ey*ey + ez*ez);
                float tr = dg - dp;
                cnt += 1.0f; ss += sig2; st += tr * tr;
            }
        }
        #pragma unroll
        for (int off = 16; off; off >>= 1) {
            cnt += __shfl_down_sync(FULL, cnt, off);
            ss  += __shfl_down_sync(FULL, ss,  off);
            st  += __shfl_down_sync(FULL, st,  off);
        }
        if (tid == 0) {
            float mvar = sqrtf(ss / cnt);
            float rmse = sqrtf(st / cnt);
            out[0] = fabsf(mvar - rmse) / mvar;
        }
        return;
    }

    {   // degenerate fallback: exact all-pairs
        float cnt = 0.0f, ss = 0.0f, st = 0.0f;
        long total = (long)N * (long)N;
        for (long p = tid; p < total; p += GNT) {
            int i = (int)(p / N), j = (int)(p - (long)i * N);
            if (i == j) continue;
            float sig2 = sig2_of_sum(__ldg(sigmas + i) + __ldg(sigmas + j));
            float t = (sig2 - begin) / interval;
            int bi = (int)floorf(t);
            bi = bi < 0 ? 0 : (bi > 9 ? 9 : bi);
            if (bi == 9) {
                float dx = y[3*i]-y[3*j], dy = y[3*i+1]-y[3*j+1], dz = y[3*i+2]-y[3*j+2];
                float dg = sqrtf(dx*dx + dy*dy + dz*dz);
                float ex = py[3*i]-py[3*j], ey = py[3*i+1]-py[3*j+1], ez = py[3*i+2]-py[3*j+2];
                float dp = sqrtf(ex*ex + ey*ey + ez*ez);
                float tr = dg - dp;
                cnt += 1.0f; ss += sig2; st += tr * tr;
            }
        }
        #pragma unroll
        for (int off = 16; off; off >>= 1) {
            cnt += __shfl_down_sync(FULL, cnt, off);
            ss  += __shfl_down_sync(FULL, ss,  off);
            st  += __shfl_down_sync(FULL, st,  off);
        }
        if ((tid & 31) == 0) { red[tid>>5][0]=cnt; red[tid>>5][1]=ss; red[tid>>5][2]=st; }
        __syncthreads();
        if (tid < 32) {
            cnt = red[tid][0]; ss = red[tid][1]; st = red[tid][2];
            #pragma unroll
            for (int off = 16; off; off >>= 1) {
                cnt += __shfl_down_sync(FULL, cnt, off);
                ss  += __shfl_down_sync(FULL, ss,  off);
                st  += __shfl_down_sync(FULL, st,  off);
            }
            if (tid == 0) {
                float mvar = sqrtf(ss / cnt);
                float rmse = sqrtf(st / cnt);
                out[0] = fabsf(mvar - rmse) / mvar;
            }
        }
    }
}

extern "C" void kernel_launch(void* const* d_in, const int* in_sizes, int n_in,
                              void* d_out, int out_size) {
    const float* sigmas = (const float*)d_in[0];
    const float* y      = (const float*)d_in[1];
    const float* py     = (const float*)d_in[2];
    int N = in_sizes[0];
    if (N <= NT * EPT)
        ENCELDDT_fast<<<1, NT>>>(sigmas, y, py, (float*)d_out, N);
    else
        ENCELDDT_generic<<<1, GNT>>>(sigmas, y, py, (float*)d_out, N);
}